// round 13
// baseline (speedup 1.0000x reference)
#include <cuda_runtime.h>

// SFAM_43490838839386: f = clip(tanh(x)/||tanh(x)||_2 + 0.01*noise, -1.5, 1.5)
//                      out = tanh(einsum('bi,bij->bj', f, P))
// B=4096, D=256, S=256, fp32. HBM-bound: P = 1.07 GB read once.
// R9: two-kernel split. Kernel A (warp-per-sample, barrier-free) precomputes
// f into __device__ scratch. Kernel B = R4's streaming shape (8192 CTAs,
// half-split, cp.async PF=4, __ldcs) with phase-1 reduced to a 1KB L2-hit
// f load -> pure-stream SASS, denser LDG issue.

#define Dk 256
#define Sk 256
#define Bk 4096
#define NOISE_STD 0.01f
#define EPSN 1e-12f
#define PF 4   // prefetched i-iterations per thread (kernel B)

__device__ float f_glob[Bk * Dk];   // 4 MB scratch (sanctioned __device__ global)

// ---------------- Kernel A: compute f, one warp per sample, no barriers ------
__global__ __launch_bounds__(256)
void sfam_prep(const float* __restrict__ raw,
               const float* __restrict__ noise)
{
    const int warp = (blockIdx.x * 256 + threadIdx.x) >> 5;   // sample id
    const int lane = threadIdx.x & 31;

    const float4* r4 = reinterpret_cast<const float4*>(raw   + (size_t)warp * Dk);
    const float4* n4 = reinterpret_cast<const float4*>(noise + (size_t)warp * Dk);

    float4 rv0 = r4[lane];            // d = 4*lane .. 4*lane+3
    float4 rv1 = r4[32 + lane];       // d = 128 + 4*lane ..
    float4 nv0 = n4[lane];
    float4 nv1 = n4[32 + lane];

    float t0x = tanhf(rv0.x), t0y = tanhf(rv0.y), t0z = tanhf(rv0.z), t0w = tanhf(rv0.w);
    float t1x = tanhf(rv1.x), t1y = tanhf(rv1.y), t1z = tanhf(rv1.z), t1w = tanhf(rv1.w);

    float sq = t0x*t0x + t0y*t0y + t0z*t0z + t0w*t0w
             + t1x*t1x + t1y*t1y + t1z*t1z + t1w*t1w;
    #pragma unroll
    for (int o = 16; o > 0; o >>= 1)
        sq += __shfl_xor_sync(0xffffffffu, sq, o);

    const float inv = 1.0f / fmaxf(sqrtf(sq), EPSN);

    float4 f0, f1;
    f0.x = fminf(fmaxf(fmaf(t0x, inv, NOISE_STD * nv0.x), -1.5f), 1.5f);
    f0.y = fminf(fmaxf(fmaf(t0y, inv, NOISE_STD * nv0.y), -1.5f), 1.5f);
    f0.z = fminf(fmaxf(fmaf(t0z, inv, NOISE_STD * nv0.z), -1.5f), 1.5f);
    f0.w = fminf(fmaxf(fmaf(t0w, inv, NOISE_STD * nv0.w), -1.5f), 1.5f);
    f1.x = fminf(fmaxf(fmaf(t1x, inv, NOISE_STD * nv1.x), -1.5f), 1.5f);
    f1.y = fminf(fmaxf(fmaf(t1y, inv, NOISE_STD * nv1.y), -1.5f), 1.5f);
    f1.z = fminf(fmaxf(fmaf(t1z, inv, NOISE_STD * nv1.z), -1.5f), 1.5f);
    f1.w = fminf(fmaxf(fmaf(t1w, inv, NOISE_STD * nv1.w), -1.5f), 1.5f);

    float4* fg = reinterpret_cast<float4*>(f_glob + (size_t)warp * Dk);
    fg[lane]      = f0;
    fg[32 + lane] = f1;
}

// ---------------- Kernel B: hot streaming GEMV --------------------------------
__global__ __launch_bounds__(256, 8)
void sfam_stream(const float* __restrict__ proj,
                 float* __restrict__ out)
{
    __shared__ float  f_sh[Dk];
    __shared__ float  red[8 * 128];
    __shared__ float4 pf_buf[PF][256];

    const int b    = blockIdx.x >> 1;
    const int half = blockIdx.x & 1;
    const int tid  = threadIdx.x;

    const int jg     = tid & 31;   // float4 column group within half
    const int islice = tid >> 5;   // 0..7

    const float* pbase = proj + (size_t)b * Dk * Sk + (size_t)half * 128 + (size_t)jg * 4;

    // Fire-and-forget prefetch of first PF iterations of P.
    {
        unsigned sbase = (unsigned)__cvta_generic_to_shared(&pf_buf[0][tid]);
        #pragma unroll
        for (int k = 0; k < PF; k++) {
            const float* g = pbase + (size_t)(islice + 8 * k) * Sk;
            asm volatile("cp.async.cg.shared.global [%0], [%1], 16;\n"
                         :: "r"(sbase + k * 256 * 16), "l"(g));
        }
        asm volatile("cp.async.commit_group;\n");
    }

    // Short head: pull precomputed f (1 KB, L2-hit for one of the two halves).
    f_sh[tid] = f_glob[(size_t)b * Dk + tid];
    __syncthreads();

    float4 acc = make_float4(0.f, 0.f, 0.f, 0.f);

    asm volatile("cp.async.wait_group 0;\n" ::: "memory");
    #pragma unroll
    for (int k = 0; k < PF; k++) {
        const float  fi = f_sh[islice + 8 * k];
        const float4 p  = pf_buf[k][tid];
        acc.x = fmaf(fi, p.x, acc.x);
        acc.y = fmaf(fi, p.y, acc.y);
        acc.z = fmaf(fi, p.z, acc.z);
        acc.w = fmaf(fi, p.w, acc.w);
    }

    #pragma unroll 4
    for (int i = islice + 8 * PF; i < Dk; i += 8) {
        const float  fi = f_sh[i];
        const float4 p  = __ldcs(reinterpret_cast<const float4*>(pbase + (size_t)i * Sk));
        acc.x = fmaf(fi, p.x, acc.x);
        acc.y = fmaf(fi, p.y, acc.y);
        acc.z = fmaf(fi, p.z, acc.z);
        acc.w = fmaf(fi, p.w, acc.w);
    }

    *reinterpret_cast<float4*>(&red[islice * 128 + jg * 4]) = acc;
    __syncthreads();

    if (tid < 128) {
        float h = 0.f;
        #pragma unroll
        for (int s = 0; s < 8; s++) h += red[s * 128 + tid];
        __stcs(&out[(size_t)b * Sk + (size_t)half * 128 + tid], tanhf(h));
    }
}

extern "C" void kernel_launch(void* const* d_in, const int* in_sizes, int n_in,
                              void* d_out, int out_size)
{
    const float* raw   = (const float*)d_in[0];
    const float* proj  = (const float*)d_in[1];
    const float* noise = (const float*)d_in[2];
    float* out = (float*)d_out;

    const int B = in_sizes[0] / Dk;            // 4096
    sfam_prep  <<<B / 8, 256>>>(raw, noise);   // 8 samples (warps) per CTA
    sfam_stream<<<2 * B, 256>>>(proj, out);
}

// round 15
// speedup vs baseline: 1.0796x; 1.0796x over previous
#include <cuda_runtime.h>

// SFAM_43490838839386: f = clip(tanh(x)/||tanh(x)||_2 + 0.01*noise, -1.5, 1.5)
//                      out = tanh(einsum('bi,bij->bj', f, P))
// B=4096, D=256, S=256, fp32. HBM-bound: P = 1.07 GB read once.
// R13: wall-optimal shape. In the timed (graph-replay) regime raw/noise/out
// are L2-resident, so no prefetch machinery: lean R2 shape (8192 CTAs,
// half-split, 5KB smem, occ 8), one barrier removed from phase 1,
// __ldcs on P (evict-first, protects L2 residents), __stcs on out.

#define Dk 256
#define Sk 256
#define NOISE_STD 0.01f
#define EPSN 1e-12f

__global__ __launch_bounds__(256, 8)
void sfam_kernel(const float* __restrict__ raw,
                 const float* __restrict__ proj,
                 const float* __restrict__ noise,
                 float* __restrict__ out)
{
    __shared__ float f_sh[Dk];
    __shared__ float red[8 * 128];
    __shared__ float warp_sums[8];

    const int b    = blockIdx.x >> 1;   // sample
    const int half = blockIdx.x & 1;    // which 128-column half
    const int tid  = threadIdx.x;

    // ---------------- Phase 1: build f[b, :] in shared (L2-hit loads) --------
    const float rawv   = raw  [(size_t)b * Dk + tid];
    const float noisev = noise[(size_t)b * Dk + tid];

    const float t = tanhf(rawv);
    float sq = t * t;
    #pragma unroll
    for (int o = 16; o > 0; o >>= 1)
        sq += __shfl_xor_sync(0xffffffffu, sq, o);
    if ((tid & 31) == 0) warp_sums[tid >> 5] = sq;
    __syncthreads();

    // Every thread sums the 8 warp partials itself (broadcast LDS, no 2nd bar).
    float nrm = 0.f;
    #pragma unroll
    for (int w = 0; w < 8; w++) nrm += warp_sums[w];
    const float inv = 1.0f / fmaxf(sqrtf(nrm), EPSN);

    float fv = fmaf(t, inv, NOISE_STD * noisev);
    fv = fminf(fmaxf(fv, -1.5f), 1.5f);
    f_sh[tid] = fv;
    __syncthreads();

    // ---------------- Phase 2: hashed[j] = sum_i f[i] * P[b,i,j] -------------
    // 32 column-groups (float4) x 8 i-slices. Warp = one i-slice; lanes cover
    // 512B contiguous per row -> fully coalesced 128B transactions.
    const int jg     = tid & 31;
    const int islice = tid >> 5;

    const float* pbase = proj + (size_t)b * Dk * Sk + (size_t)half * 128 + (size_t)jg * 4;
    float4 acc = make_float4(0.f, 0.f, 0.f, 0.f);

    #pragma unroll 8
    for (int i = islice; i < Dk; i += 8) {
        const float  fi = f_sh[i];
        const float4 p  = __ldcs(reinterpret_cast<const float4*>(pbase + (size_t)i * Sk));
        acc.x = fmaf(fi, p.x, acc.x);
        acc.y = fmaf(fi, p.y, acc.y);
        acc.z = fmaf(fi, p.z, acc.z);
        acc.w = fmaf(fi, p.w, acc.w);
    }

    *reinterpret_cast<float4*>(&red[islice * 128 + jg * 4]) = acc;
    __syncthreads();

    // Reduce 8 slices per column, final tanh, streaming store.
    if (tid < 128) {
        float h = 0.f;
        #pragma unroll
        for (int s = 0; s < 8; s++) h += red[s * 128 + tid];
        __stcs(&out[(size_t)b * Sk + (size_t)half * 128 + tid], tanhf(h));
    }
}

extern "C" void kernel_launch(void* const* d_in, const int* in_sizes, int n_in,
                              void* d_out, int out_size)
{
    const float* raw   = (const float*)d_in[0];
    const float* proj  = (const float*)d_in[1];
    const float* noise = (const float*)d_in[2];
    float* out = (float*)d_out;

    const int B = in_sizes[0] / Dk;  // 4096
    sfam_kernel<<<2 * B, 256>>>(raw, proj, noise, out);
}